// round 15
// baseline (speedup 1.0000x reference)
#include <cuda_runtime.h>
#include <math.h>

#define H_FIXED 16
#define K_FIXED 5
#define MAX_S 4096
#define L4_OF(S) (2 * (S) + 8)              // per-head padded length (mult of 4)
#define MAX_L4 (2 * MAX_S + 8)

// Single shifted reversed-scores table:
//   tab[h][m] = revsc[h][m + a*],  revsc[h][q] = scores[h][2S - q],
//   a* = (S - 14) & 3.
// In the expand grid, every window base idx0 = S-14-i0+j satisfies
// idx0 ≡ a* (mod 4), so element (idx0 - a*) is 16B-aligned in tab — one
// phase copy suffices for aligned float4 loads.
__device__ __align__(16) float g_tab[H_FIXED * MAX_L4];

// Kernel 1: tab[h][q - a*] = revsc[h][q], coalesced single-copy build.
__global__ void tisa_scores_kernel(const float* __restrict__ off,
                                   const float* __restrict__ wid,
                                   const float* __restrict__ amp,
                                   int S) {
    const int L = 2 * S + 1;
    const int total = H_FIXED * L;
    int idx = blockIdx.x * blockDim.x + threadIdx.x;
    if (idx >= total) return;
    int h = idx / L;
    int q = idx - h * L;
    float rel = (float)(S - q);            // revsc[q] = scores[2S - q]
    float sum = 0.0f;
#pragma unroll
    for (int k = 0; k < K_FIXED; k++) {
        float o = off[k * H_FIXED + h];
        float w = fabsf(wid[k * H_FIXED + h]);
        float a = amp[k * H_FIXED + h];
        float d = o - rel;
        sum += a * __expf(-w * d * d);
    }
    const int a_star = (S - 14) & 3;
    const int m = q - a_star;
    if (m >= 0)
        g_tab[(size_t)h * L4_OF(S) + m] = sum;
}

// Kernel 2: sliding-window pipelined expansion (round-8 proven structure,
// single-phase table).
#define R_ROWS 16
#define GS 4
#define TPB 256

__global__ void __launch_bounds__(TPB)
tisa_expand_kernel(float4* __restrict__ out, int S) {
    const int h   = blockIdx.z;
    const int seg = blockIdx.y;
    const int j4  = blockIdx.x * TPB + threadIdx.x;   // float4 column index
    const int S4  = S >> 2;
    if (j4 >= S4) return;
    const int j = j4 << 2;

    const int i0 = seg * (GS * R_ROWS);

    // Window base for t=0 (lowest source index of first group)
    const int idx0   = (S + 1) - (i0 + R_ROWS - 1) + j;  // = S - 14 - i0 + j
    const int a_star = (S - 14) & 3;                     // grid-wide constant
    const int L4 = L4_OF(S);
    // T[p] = revsc[idx0 + 4p ..] as aligned float4 (tab absorbs the shift)
    const float4* __restrict__ T =
        (const float4*)(g_tab + (size_t)h * L4 + (idx0 - a_star));

    float w[20];
#pragma unroll
    for (int c = 0; c < 5; c++) {           // preload window of first group
        float4 t4 = __ldg(T + c);
        w[c * 4 + 0] = t4.x;
        w[c * 4 + 1] = t4.y;
        w[c * 4 + 2] = t4.z;
        w[c * 4 + 3] = t4.w;
    }

    float4* __restrict__ dst = out + ((size_t)h * S + i0) * (size_t)S4 + j4;

#pragma unroll
    for (int t = 0; t < GS; t++) {
        // Prefetch next window's 4 new chunks before this group's stores
        float4 n0, n1, n2, n3;
        if (t < GS - 1) {
            const float4* Tn = T - 4 * (t + 1);
            n0 = __ldg(Tn + 0);
            n1 = __ldg(Tn + 1);
            n2 = __ldg(Tn + 2);
            n3 = __ldg(Tn + 3);
        }

        // 16 back-to-back streaming stores for group t
#pragma unroll
        for (int r = 0; r < R_ROWS; r++) {
            int k = (R_ROWS - 1) - r;       // 15 - r
            float4 o;
            o.x = w[k + 0];
            o.y = w[k + 1];
            o.z = w[k + 2];
            o.w = w[k + 3];
            __stcs(dst + (size_t)(t * R_ROWS + r) * S4, o);
        }

        // Slide window down by 16: keep old w[0..3] as new w[16..19]
        if (t < GS - 1) {
            w[16] = w[0];  w[17] = w[1];  w[18] = w[2];  w[19] = w[3];
            w[0]  = n0.x;  w[1]  = n0.y;  w[2]  = n0.z;  w[3]  = n0.w;
            w[4]  = n1.x;  w[5]  = n1.y;  w[6]  = n1.z;  w[7]  = n1.w;
            w[8]  = n2.x;  w[9]  = n2.y;  w[10] = n2.z;  w[11] = n2.w;
            w[12] = n3.x;  w[13] = n3.y;  w[14] = n3.z;  w[15] = n3.w;
        }
    }
}

extern "C" void kernel_launch(void* const* d_in, const int* in_sizes, int n_in,
                              void* d_out, int out_size) {
    // Inputs (metadata order): seq_len (scalar, unused), offsets [K,H],
    // widths [K,H], amplitudes [K,H]
    const float* off = (const float*)d_in[1];
    const float* wid = (const float*)d_in[2];
    const float* amp = (const float*)d_in[3];

    // out_size = H * S * S; H = 16 fixed for this problem
    int S = (int)llround(sqrt((double)out_size / (double)H_FIXED));
    int S4 = S >> 2;

    // Kernel 1: single-phase shifted table build
    {
        int total = H_FIXED * (2 * S + 1);
        int threads = 256;
        int blocks = (total + threads - 1) / threads;
        tisa_scores_kernel<<<blocks, threads>>>(off, wid, amp, S);
    }

    // Kernel 2: pipelined Toeplitz expansion (plain launch, no PDL)
    {
        dim3 grid((S4 + TPB - 1) / TPB, S / (R_ROWS * GS), H_FIXED);
        tisa_expand_kernel<<<grid, TPB>>>((float4*)d_out, S);
    }
}